// round 15
// baseline (speedup 1.0000x reference)
#include <cuda_runtime.h>
#include <cuda_fp16.h>
#include <math.h>
#include <stdint.h>

#define M_TOK 16384
#define D_IN  1024
#define D_HID 256
#define N_EXP 64

// Packed hi/lo fp16 weight splits, kpair-PERMUTED within each 8-kpair group:
// group inner order [0,4,1,5,2,6,3,7] so (q, q+4) sit adjacent -> LDS.128.
__device__ uint2 g_w1p[D_HID * (D_IN / 2)];   // W1^T packed [256][512]
__device__ uint2 g_w2p[N_EXP * (D_HID / 2)];  // W2^T packed [64][128]

// ---------------------------------------------------------------------------
__device__ __forceinline__ uint32_t smem_u32(const void* p) {
    uint32_t a;
    asm("{ .reg .u64 t; cvta.to.shared.u64 t, %1; cvt.u32.u64 %0, t; }"
        : "=r"(a) : "l"(p));
    return a;
}
__device__ __forceinline__ void cp16(uint32_t dst, const void* src) {
    asm volatile("cp.async.cg.shared.global [%0], [%1], 16;"
                 :: "r"(dst), "l"(src));
}
__device__ __forceinline__ uint32_t pack_h2(float a, float b) {
    __half2 h = __floats2half2_rn(a, b);
    return *(uint32_t*)&h;
}
__device__ __forceinline__ uint2 split2(float v0, float v1) {
    float h0 = __half2float(__float2half_rn(v0));
    float h1 = __half2float(__float2half_rn(v1));
    uint2 u;
    u.x = pack_h2(h0, h1);
    u.y = pack_h2(v0 - h0, v1 - h1);
    return u;
}
__device__ __forceinline__ void mma_f16(float* c, uint32_t a0, uint32_t a1,
                                        uint32_t a2, uint32_t a3,
                                        uint32_t b0, uint32_t b1) {
    asm volatile(
        "mma.sync.aligned.m16n8k16.row.col.f32.f16.f16.f32 "
        "{%0,%1,%2,%3}, {%4,%5,%6,%7}, {%8,%9}, {%0,%1,%2,%3};"
        : "+f"(c[0]), "+f"(c[1]), "+f"(c[2]), "+f"(c[3])
        : "r"(a0), "r"(a1), "r"(a2), "r"(a3), "r"(b0), "r"(b1));
}

// ---------------------------------------------------------------------------
// Prep: transpose + fp16 hi/lo split + pack (permuted kpair order)
// ---------------------------------------------------------------------------
__global__ void __launch_bounds__(256)
prep_w(const float* __restrict__ W1, const float* __restrict__ W2) {
    __shared__ float t[32][33];
    const int z = blockIdx.z;
    if (z == 1 && (blockIdx.x >= 2 || blockIdx.y >= 8)) return;

    const int n0 = blockIdx.x * 32;
    const int k0 = blockIdx.y * 32;
    const int tx = threadIdx.x & 31;
    const int ty = threadIdx.x >> 5;
    const float* W    = z ? W2 : W1;
    const int   ncols = z ? N_EXP : D_HID;

    #pragma unroll
    for (int i = 0; i < 32; i += 8)
        t[ty + i][tx] = W[(k0 + ty + i) * ncols + n0 + tx];
    __syncthreads();

    const int nn = threadIdx.x >> 3;
    const int jj = threadIdx.x & 7;
    uint2* dst = z ? g_w2p : g_w1p;
    const int kp_pitch = z ? (D_HID / 2) : (D_IN / 2);
    #pragma unroll
    for (int q = 0; q < 2; q++) {
        const int p     = jj * 2 + q;                 // local kpair 0..15
        const int inner = p & 7;
        const int pos   = (p & 8) | ((inner & 3) * 2) | (inner >> 2);
        dst[(size_t)(n0 + nn) * kp_pitch + k0 / 2 + pos] =
            split2(t[2 * p][nn], t[2 * p + 1][nn]);
    }
}

// ---------------------------------------------------------------------------
// Fused kernel (R9 inner loop, KC=64 per barrier): 256 thr, warp 32x128.
// B ring: 2 stages x 2 sub-tiles (sub-tile = 256 rows x 16 kpairs, PITCH 24).
// One wait+barrier per 64 K-columns (16 total instead of 32).
// Phase2: W2s [0,69632)  Ls1 [69632,+33280)  Ls2 [102912,+33280)
// ---------------------------------------------------------------------------
#define PITCH    24
#define W2_PITCH 136
#define B_SUB    49152
#define SMEM_BYTES (4 * B_SUB)          // 196608; phase2 needs 136192

__global__ void __launch_bounds__(256)
fused_gate(const float* __restrict__ x, const float* __restrict__ b1,
           const float* __restrict__ b2, float* __restrict__ out) {
    extern __shared__ char smc[];
    __shared__ float sb2[64];
    __shared__ float sg1[128], sg2[128];
    __shared__ int   si1[128], si2[128];

    const int tid  = threadIdx.x;
    const int lane = tid & 31;
    const int grp  = lane >> 2;
    const int kq   = lane & 3;
    const int w    = tid >> 5;
    const int wm   = (w & 3) * 32;
    const int wn   = (w >> 2) * 128;       // gemm1 N-half == gemm2 K-half
    const int m0   = blockIdx.x * 128;

    const uint32_t uB = smem_u32(smc);
    if (tid < 64) sb2[tid] = b2[tid];

    const int frow = tid >> 3;
    const int fg   = tid & 7;

    // Fill one 64-col stage = sub-tiles (2*stage, 2*stage+1); one commit.
#define FILL_STAGE(stage, kb64)                                               \
    {                                                                         \
        _Pragma("unroll")                                                     \
        for (int h = 0; h < 2; h++) {                                         \
            const uint32_t dstb = uB + ((stage) * 2 + h) * B_SUB;             \
            const int kp0 = (kb64) * 32 + h * 16;                             \
            _Pragma("unroll")                                                 \
            for (int r = 0; r < 8; r++) {                                     \
                int row = frow + r * 32;                                      \
                cp16(dstb + (uint32_t)(row * PITCH + fg * 2) * 8,             \
                     &g_w1p[(size_t)row * 512 + kp0 + fg * 2]);               \
            }                                                                 \
        }                                                                     \
        asm volatile("cp.async.commit_group;" ::: "memory");                  \
    }

    // x row pointers for this thread's A-fragment rows
    const float* xr[4];
    #pragma unroll
    for (int i = 0; i < 4; i++)
        xr[i] = x + (size_t)(m0 + wm + i * 8 + grp) * D_IN + kq * 2;

    // sk in 16-kpair (32-col) units
#define LOAD_X(sk)                                                            \
    {                                                                         \
        const int nk = (sk) * 32;                                             \
        _Pragma("unroll")                                                     \
        for (int s = 0; s < 2; s++)                                           \
            _Pragma("unroll")                                                 \
            for (int mt = 0; mt < 2; mt++)                                    \
                _Pragma("unroll")                                             \
                for (int j = 0; j < 4; j++)                                   \
                    xv[(s * 2 + mt) * 4 + j] =                                \
                        *(const float2*)(xr[2 * mt + (j & 1)] + nk +          \
                                         s * 16 + (j >> 1) * 8);              \
    }

#define SPLIT_X(FRN)                                                          \
    {                                                                         \
        _Pragma("unroll")                                                     \
        for (int i = 0; i < 16; i++) FRN[i] = split2(xv[i].x, xv[i].y);       \
    }

    // R9's exact inner-loop order (mt-inner, hh/hl/lh consecutive per mt)
#define MMA_SEC(FRC, SUB)                                                     \
    {                                                                         \
        const uint2* const cB = (const uint2*)(smc + (SUB) * B_SUB);          \
        _Pragma("unroll")                                                     \
        for (int s = 0; s < 2; s++) {                                         \
            _Pragma("unroll")                                                 \
            for (int nt = 0; nt < 16; nt++) {                                 \
                const int n = wn + nt * 8 + grp;                              \
                uint4 bv = *(const uint4*)&cB[n * PITCH + s * 8 + 2 * kq];    \
                _Pragma("unroll")                                             \
                for (int mt = 0; mt < 2; mt++) {                              \
                    const uint2* f = &FRC[(s * 2 + mt) * 4];                  \
                    mma_f16(c[mt][nt], f[0].x, f[1].x, f[2].x, f[3].x,        \
                            bv.x, bv.z);                                      \
                    mma_f16(c[mt][nt], f[0].x, f[1].x, f[2].x, f[3].x,        \
                            bv.y, bv.w);                                      \
                    mma_f16(c[mt][nt], f[0].y, f[1].y, f[2].y, f[3].y,        \
                            bv.x, bv.z);                                      \
                }                                                             \
            }                                                                 \
        }                                                                     \
    }

    float c[2][16][4] = {};
    float2 xv[16];
    uint2  fr0[16], fr1[16];

    // prologue: stage 0 fill + first sub-tile's x
    FILL_STAGE(0, 0);
    LOAD_X(0);
    SPLIT_X(fr0);

    int st = 0;
    #pragma unroll 1
    for (int kb64 = 0; kb64 < 16; kb64++) {
        asm volatile("cp.async.wait_group 0;" ::: "memory");
        __syncthreads();
        if (kb64 < 15) FILL_STAGE(st ^ 1, kb64 + 1);

        LOAD_X(2 * kb64 + 1);              // sub1 of this stage
        MMA_SEC(fr0, 2 * st + 0);
        SPLIT_X(fr1);

        if (kb64 < 15) LOAD_X(2 * kb64 + 2);   // sub0 of next stage
        MMA_SEC(fr1, 2 * st + 1);
        if (kb64 < 15) SPLIT_X(fr0);

        st ^= 1;
    }

    // mainloop fully done (all warps) before W2 fill reuses B-stage smem
    __syncthreads();

    // ---- load W2 tile into smem [0,69632)
    uint2* const W2s = (uint2*)smc;
    {
        #pragma unroll
        for (int r = 0; r < 16; r++) {
            int idx = tid + 256 * r;
            int n = idx >> 6, kpp = (idx & 63) * 2;
            cp16(uB + (uint32_t)(n * W2_PITCH + kpp) * 8,
                 &g_w2p[(size_t)n * 128 + kpp]);
        }
        asm volatile("cp.async.commit_group;" ::: "memory");
    }

    // ---- tanh + b1, re-split: gemm2 A-fragments in registers
    uint2 ph[2][16], pl[2][16];
    #pragma unroll
    for (int mt = 0; mt < 2; mt++) {
        #pragma unroll
        for (int nt = 0; nt < 16; nt++) {
            const int col = wn + nt * 8 + kq * 2;
            const float bc0 = __ldg(&b1[col]);
            const float bc1 = __ldg(&b1[col + 1]);
            float t0 = tanhf(c[mt][nt][0] + bc0);
            float t1 = tanhf(c[mt][nt][1] + bc1);
            float t2 = tanhf(c[mt][nt][2] + bc0);
            float t3 = tanhf(c[mt][nt][3] + bc1);
            ph[mt][nt] = split2(t0, t1);    // rows wm+16mt+grp
            pl[mt][nt] = split2(t2, t3);    // rows wm+16mt+grp+8
        }
    }
    asm volatile("cp.async.wait_group 0;" ::: "memory");
    __syncthreads();

    // ---- gemm2: logits partials over this warp's K-half (A from regs)
    const int kho = (w >> 2) * 64;
    float c2[2][8][4] = {};
    #pragma unroll
    for (int s = 0; s < 8; s++) {
        #pragma unroll
        for (int ntB = 0; ntB < 8; ntB++) {
            const int n = 8 * ntB + grp;
            uint4 bv = *(const uint4*)&W2s[n * W2_PITCH + kho + 8 * s + 2 * kq];
            #pragma unroll
            for (int mt = 0; mt < 2; mt++) {
                uint2 A0 = ph[mt][2 * s], A1 = pl[mt][2 * s];
                uint2 A2 = ph[mt][2 * s + 1], A3 = pl[mt][2 * s + 1];
                mma_f16(c2[mt][ntB], A0.x, A1.x, A2.x, A3.x, bv.x, bv.z);
                mma_f16(c2[mt][ntB], A0.x, A1.x, A2.x, A3.x, bv.y, bv.w);
                mma_f16(c2[mt][ntB], A0.y, A1.y, A2.y, A3.y, bv.x, bv.z);
            }
        }
    }

    // ---- write logit partials (two K-half buffers)
    float* const LsH = (float*)(smc + 69632 + (w >> 2) * 33280);
    #pragma unroll
    for (int mt = 0; mt < 2; mt++) {
        const int R0 = wm + mt * 16 + grp;
        #pragma unroll
        for (int ntB = 0; ntB < 8; ntB++) {
            const int e0 = ntB * 8 + kq * 2;
            LsH[R0 * 65 + e0]           = c2[mt][ntB][0];
            LsH[R0 * 65 + e0 + 1]       = c2[mt][ntB][1];
            LsH[(R0 + 8) * 65 + e0]     = c2[mt][ntB][2];
            LsH[(R0 + 8) * 65 + e0 + 1] = c2[mt][ntB][3];
        }
    }
    __syncthreads();

    float* const Ls1 = (float*)(smc + 69632);
    float* const Ls2 = (float*)(smc + 102912);

    // ---- top-2 + softmax (one thread per token)
    if (tid < 128) {
        float v1 = -1e30f, v2 = -1e30f;
        int   i1 = 0,      i2 = 0;
        #pragma unroll 8
        for (int e = 0; e < N_EXP; e++) {
            float v = Ls1[tid * 65 + e] + Ls2[tid * 65 + e] + sb2[e];
            if (v > v1) { v2 = v1; i2 = i1; v1 = v; i1 = e; }
            else if (v > v2) { v2 = v; i2 = e; }
        }
        float e2  = expf(v2 - v1);
        float inv = 1.0f / (1.0f + e2);
        sg1[tid] = inv;
        sg2[tid] = e2 * inv;
        si1[tid] = i1;
        si2[tid] = i2;
    }
    __syncthreads();

    // ---- write logits + gates (token = tid>>1, expert half = (tid&1)*32)
    {
        const int t  = tid >> 1;
        const int eb = (tid & 1) * 32;
        const int i1 = si1[t], i2 = si2[t];
        const float g1 = sg1[t], g2 = sg2[t];
        float* orow = &out[(size_t)(m0 + t) * N_EXP + eb];
        float* lrow = &out[(size_t)M_TOK * N_EXP + (size_t)(m0 + t) * N_EXP + eb];
        #pragma unroll
        for (int j = 0; j < 8; j++) {
            float4 lg, gt;
            float lv[4], gv[4];
            #pragma unroll
            for (int q = 0; q < 4; q++) {
                const int e = eb + j * 4 + q;
                lv[q] = Ls1[t * 65 + e] + Ls2[t * 65 + e] + sb2[e];
                gv[q] = (e == i1) ? g1 : ((e == i2) ? g2 : 0.0f);
            }
            lg.x = lv[0]; lg.y = lv[1]; lg.z = lv[2]; lg.w = lv[3];
            gt.x = gv[0]; gt.y = gv[1]; gt.z = gv[2]; gt.w = gv[3];
            *(float4*)&lrow[j * 4] = lg;
            *(float4*)&orow[j * 4] = gt;
        }
    }
}

// ---------------------------------------------------------------------------
extern "C" void kernel_launch(void* const* d_in, const int* in_sizes, int n_in,
                              void* d_out, int out_size) {
    const float* x  = (const float*)d_in[0];
    const float* W1 = (const float*)d_in[1];
    const float* b1 = (const float*)d_in[2];
    const float* W2 = (const float*)d_in[3];
    const float* b2 = (const float*)d_in[4];
    float* out = (float*)d_out;

    static int init = 0;
    if (!init) {
        cudaFuncSetAttribute(fused_gate,
                             cudaFuncAttributeMaxDynamicSharedMemorySize,
                             SMEM_BYTES);
        init = 1;
    }

    prep_w<<<dim3(8, 32, 2), 256>>>(W1, W2);
    fused_gate<<<M_TOK / 128, 256, SMEM_BYTES>>>(x, b1, b2, out);
}

// round 16
// speedup vs baseline: 1.2755x; 1.2755x over previous
#include <cuda_runtime.h>
#include <cuda_fp16.h>
#include <math.h>
#include <stdint.h>

#define M_TOK 16384
#define D_IN  1024
#define D_HID 256
#define N_EXP 64

// Packed hi/lo fp16 W1^T splits, kpair-PERMUTED within each 8-kpair group:
// group inner order [0,4,1,5,2,6,3,7] so (q, q+4) sit adjacent -> LDS.128.
__device__ uint2 g_w1p[D_HID * (D_IN / 2)];   // W1^T packed [256][512]

// ---------------------------------------------------------------------------
__device__ __forceinline__ uint32_t smem_u32(const void* p) {
    uint32_t a;
    asm("{ .reg .u64 t; cvta.to.shared.u64 t, %1; cvt.u32.u64 %0, t; }"
        : "=r"(a) : "l"(p));
    return a;
}
__device__ __forceinline__ void cp16(uint32_t dst, const void* src) {
    asm volatile("cp.async.cg.shared.global [%0], [%1], 16;"
                 :: "r"(dst), "l"(src));
}
__device__ __forceinline__ uint32_t pack_h2(float a, float b) {
    __half2 h = __floats2half2_rn(a, b);
    return *(uint32_t*)&h;
}
__device__ __forceinline__ uint2 split2(float v0, float v1) {
    float h0 = __half2float(__float2half_rn(v0));
    float h1 = __half2float(__float2half_rn(v1));
    uint2 u;
    u.x = pack_h2(h0, h1);
    u.y = pack_h2(v0 - h0, v1 - h1);
    return u;
}
__device__ __forceinline__ void mma_f16(float* c, uint32_t a0, uint32_t a1,
                                        uint32_t a2, uint32_t a3,
                                        uint32_t b0, uint32_t b1) {
    asm volatile(
        "mma.sync.aligned.m16n8k16.row.col.f32.f16.f16.f32 "
        "{%0,%1,%2,%3}, {%4,%5,%6,%7}, {%8,%9}, {%0,%1,%2,%3};"
        : "+f"(c[0]), "+f"(c[1]), "+f"(c[2]), "+f"(c[3])
        : "r"(a0), "r"(a1), "r"(a2), "r"(a3), "r"(b0), "r"(b1));
}

// ---------------------------------------------------------------------------
// Prep: W1 only — transpose + fp16 hi/lo split + pack (permuted kpair order)
// ---------------------------------------------------------------------------
__global__ void __launch_bounds__(256)
prep_w(const float* __restrict__ W1) {
    __shared__ float t[32][33];
    const int n0 = blockIdx.x * 32;
    const int k0 = blockIdx.y * 32;
    const int tx = threadIdx.x & 31;
    const int ty = threadIdx.x >> 5;

    #pragma unroll
    for (int i = 0; i < 32; i += 8)
        t[ty + i][tx] = W1[(k0 + ty + i) * D_HID + n0 + tx];
    __syncthreads();

    const int nn = threadIdx.x >> 3;
    const int jj = threadIdx.x & 7;
    #pragma unroll
    for (int q = 0; q < 2; q++) {
        const int p     = jj * 2 + q;                 // local kpair 0..15
        const int inner = p & 7;
        const int pos   = (p & 8) | ((inner & 3) * 2) | (inner >> 2);
        g_w1p[(size_t)(n0 + nn) * (D_IN / 2) + k0 / 2 + pos] =
            split2(t[2 * p][nn], t[2 * p + 1][nn]);
    }
}

// ---------------------------------------------------------------------------
// Fused kernel (R9, 88.5us): 256 thr (8 warps), M_tile=128, warp tile 32x128.
// Mainloop: B 3-stage cp.async ring (stage 49152 B, PITCH 24), A from gmem
// regs, split2 off the barrier->MMA critical path.
// Phase2: W2s [0,69632) packed in-kernel from gmem;
//         Ls1 [69632,+33280)  Ls2 [102912,+33280)
// ---------------------------------------------------------------------------
#define PITCH    24
#define W2_PITCH 136
#define B_STAGE  49152
#define SMEM_BYTES 147456

__global__ void __launch_bounds__(256)
fused_gate(const float* __restrict__ x, const float* __restrict__ b1,
           const float* __restrict__ W2, const float* __restrict__ b2,
           float* __restrict__ out) {
    extern __shared__ char smc[];
    __shared__ float sb2[64];
    __shared__ float sg1[128], sg2[128];
    __shared__ int   si1[128], si2[128];

    const int tid  = threadIdx.x;
    const int lane = tid & 31;
    const int grp  = lane >> 2;
    const int kq   = lane & 3;
    const int w    = tid >> 5;
    const int wm   = (w & 3) * 32;
    const int wn   = (w >> 2) * 128;       // gemm1 N-half == gemm2 K-half
    const int m0   = blockIdx.x * 128;

    const uint32_t uB = smem_u32(smc);
    if (tid < 64) sb2[tid] = b2[tid];

    const int frow = tid >> 3;
    const int fg   = tid & 7;

#define FILL_B(stage, kb)                                                     \
    {                                                                         \
        const uint32_t dstb = uB + (stage) * B_STAGE;                         \
        _Pragma("unroll")                                                     \
        for (int r = 0; r < 8; r++) {                                         \
            int row = frow + r * 32;                                          \
            cp16(dstb + (uint32_t)(row * PITCH + fg * 2) * 8,                 \
                 &g_w1p[(size_t)row * 512 + (kb) * 16 + fg * 2]);             \
        }                                                                     \
        asm volatile("cp.async.commit_group;" ::: "memory");                  \
    }

    // x row pointers for this thread's A-fragment rows
    const float* xr[4];
    #pragma unroll
    for (int i = 0; i < 4; i++)
        xr[i] = x + (size_t)(m0 + wm + i * 8 + grp) * D_IN + kq * 2;

#define LOAD_X(kb)                                                            \
    {                                                                         \
        const int nk = (kb) * 32;                                             \
        _Pragma("unroll")                                                     \
        for (int s = 0; s < 2; s++)                                           \
            _Pragma("unroll")                                                 \
            for (int mt = 0; mt < 2; mt++)                                    \
                _Pragma("unroll")                                             \
                for (int j = 0; j < 4; j++)                                   \
                    xv[(s * 2 + mt) * 4 + j] =                                \
                        *(const float2*)(xr[2 * mt + (j & 1)] + nk +          \
                                         s * 16 + (j >> 1) * 8);              \
    }

#define SPLIT_X(FRN)                                                          \
    {                                                                         \
        _Pragma("unroll")                                                     \
        for (int i = 0; i < 16; i++) FRN[i] = split2(xv[i].x, xv[i].y);       \
    }

#define MMA_SEC(FRC)                                                          \
    {                                                                         \
        const uint2* const cB = (const uint2*)(smc + st * B_STAGE);           \
        _Pragma("unroll")                                                     \
        for (int s = 0; s < 2; s++) {                                         \
            _Pragma("unroll")                                                 \
            for (int nt = 0; nt < 16; nt++) {                                 \
                const int n = wn + nt * 8 + grp;                              \
                uint4 bv = *(const uint4*)&cB[n * PITCH + s * 8 + 2 * kq];    \
                _Pragma("unroll")                                             \
                for (int mt = 0; mt < 2; mt++) {                              \
                    const uint2* f = &fr_cur[(s * 2 + mt) * 4];               \
                    mma_f16(c[mt][nt], f[0].x, f[1].x, f[2].x, f[3].x,        \
                            bv.x, bv.z);                                      \
                    mma_f16(c[mt][nt], f[0].x, f[1].x, f[2].x, f[3].x,        \
                            bv.y, bv.w);                                      \
                    mma_f16(c[mt][nt], f[0].y, f[1].y, f[2].y, f[3].y,        \
                            bv.x, bv.z);                                      \
                }                                                             \
            }                                                                 \
        }                                                                     \
    }

#define STEP(kb, FRC, FRN, WAITN, DOFILL, DOPREF)                             \
    {                                                                         \
        asm volatile("cp.async.wait_group " #WAITN ";" ::: "memory");         \
        __syncthreads();                                                      \
        if (DOFILL) { int nst = (st < 1) ? 2 : st - 1; FILL_B(nst, (kb) + 2); } \
        if (DOPREF) LOAD_X((kb) + 1);                                         \
        { const uint2* const fr_cur = FRC; MMA_SEC(FRC); }                    \
        if (DOPREF) SPLIT_X(FRN);                                             \
        st = (st + 1 < 3) ? st + 1 : 0;                                       \
    }

    float c[2][16][4] = {};
    float2 xv[16];
    uint2  fr0[16], fr1[16];

    // prologue
    FILL_B(0, 0);
    FILL_B(1, 1);
    LOAD_X(0);
    SPLIT_X(fr0);

    int st = 0;
    #pragma unroll 1
    for (int kb2 = 0; kb2 < 15; kb2++) {
        const int kb = 2 * kb2;
        STEP(kb,     fr0, fr1, 1, 1, 1);
        STEP(kb + 1, fr1, fr0, 1, 1, 1);
    }
    STEP(30, fr0, fr1, 1, 0, 1);
    STEP(31, fr1, fr0, 0, 0, 0);

    // mainloop fully done (all warps) before W2 pack reuses B-stage smem
    __syncthreads();

    // ---- pack W2 into smem [0,69632) directly from gmem (no prep pass)
    // thread -> expert n = tid&63, kpair block = (tid>>6)*32 (32 kpairs each)
    uint2* const W2s = (uint2*)smc;
    {
        const int n   = tid & 63;
        const int kpb = (tid >> 6) * 32;
        #pragma unroll 4
        for (int p = 0; p < 32; p++) {
            const int kp    = kpb + p;
            const int inner = kp & 7;
            const int pos   = (kp & ~7) | ((inner & 3) * 2) | (inner >> 2);
            float v0 = __ldg(&W2[(2 * kp) * N_EXP + n]);
            float v1 = __ldg(&W2[(2 * kp + 1) * N_EXP + n]);
            W2s[n * W2_PITCH + pos] = split2(v0, v1);
        }
    }

    // ---- tanh + b1, re-split: gemm2 A-fragments in registers
    uint2 ph[2][16], pl[2][16];
    #pragma unroll
    for (int mt = 0; mt < 2; mt++) {
        #pragma unroll
        for (int nt = 0; nt < 16; nt++) {
            const int col = wn + nt * 8 + kq * 2;
            const float bc0 = __ldg(&b1[col]);
            const float bc1 = __ldg(&b1[col + 1]);
            float t0 = tanhf(c[mt][nt][0] + bc0);
            float t1 = tanhf(c[mt][nt][1] + bc1);
            float t2 = tanhf(c[mt][nt][2] + bc0);
            float t3 = tanhf(c[mt][nt][3] + bc1);
            ph[mt][nt] = split2(t0, t1);    // rows wm+16mt+grp
            pl[mt][nt] = split2(t2, t3);    // rows wm+16mt+grp+8
        }
    }
    __syncthreads();

    // ---- gemm2: logits partials over this warp's K-half (A from regs)
    const int kho = (w >> 2) * 64;
    float c2[2][8][4] = {};
    #pragma unroll
    for (int s = 0; s < 8; s++) {
        #pragma unroll
        for (int ntB = 0; ntB < 8; ntB++) {
            const int n = 8 * ntB + grp;
            uint4 bv = *(const uint4*)&W2s[n * W2_PITCH + kho + 8 * s + 2 * kq];
            #pragma unroll
            for (int mt = 0; mt < 2; mt++) {
                uint2 A0 = ph[mt][2 * s], A1 = pl[mt][2 * s];
                uint2 A2 = ph[mt][2 * s + 1], A3 = pl[mt][2 * s + 1];
                mma_f16(c2[mt][ntB], A0.x, A1.x, A2.x, A3.x, bv.x, bv.z);
                mma_f16(c2[mt][ntB], A0.x, A1.x, A2.x, A3.x, bv.y, bv.w);
                mma_f16(c2[mt][ntB], A0.y, A1.y, A2.y, A3.y, bv.x, bv.z);
            }
        }
    }

    // ---- write logit partials (two K-half buffers)
    float* const LsH = (float*)(smc + 69632 + (w >> 2) * 33280);
    #pragma unroll
    for (int mt = 0; mt < 2; mt++) {
        const int R0 = wm + mt * 16 + grp;
        #pragma unroll
        for (int ntB = 0; ntB < 8; ntB++) {
            const int e0 = ntB * 8 + kq * 2;
            LsH[R0 * 65 + e0]           = c2[mt][ntB][0];
            LsH[R0 * 65 + e0 + 1]       = c2[mt][ntB][1];
            LsH[(R0 + 8) * 65 + e0]     = c2[mt][ntB][2];
            LsH[(R0 + 8) * 65 + e0 + 1] = c2[mt][ntB][3];
        }
    }
    __syncthreads();

    float* const Ls1 = (float*)(smc + 69632);
    float* const Ls2 = (float*)(smc + 102912);

    // ---- top-2 + softmax (one thread per token)
    if (tid < 128) {
        float v1 = -1e30f, v2 = -1e30f;
        int   i1 = 0,      i2 = 0;
        #pragma unroll 8
        for (int e = 0; e < N_EXP; e++) {
            float v = Ls1[tid * 65 + e] + Ls2[tid * 65 + e] + sb2[e];
            if (v > v1) { v2 = v1; i2 = i1; v1 = v; i1 = e; }
            else if (v > v2) { v2 = v; i2 = e; }
        }
        float e2  = expf(v2 - v1);
        float inv = 1.0f / (1.0f + e2);
        sg1[tid] = inv;
        sg2[tid] = e2 * inv;
        si1[tid] = i1;
        si2[tid] = i2;
    }
    __syncthreads();

    // ---- write logits + gates (token = tid>>1, expert half = (tid&1)*32)
    {
        const int t  = tid >> 1;
        const int eb = (tid & 1) * 32;
        const int i1 = si1[t], i2 = si2[t];
        const float g1 = sg1[t], g2 = sg2[t];
        float* orow = &out[(size_t)(m0 + t) * N_EXP + eb];
        float* lrow = &out[(size_t)M_TOK * N_EXP + (size_t)(m0 + t) * N_EXP + eb];
        #pragma unroll
        for (int j = 0; j < 8; j++) {
            float4 lg, gt;
            float lv[4], gv[4];
            #pragma unroll
            for (int q = 0; q < 4; q++) {
                const int e = eb + j * 4 + q;
                lv[q] = Ls1[t * 65 + e] + Ls2[t * 65 + e] + sb2[e];
                gv[q] = (e == i1) ? g1 : ((e == i2) ? g2 : 0.0f);
            }
            lg.x = lv[0]; lg.y = lv[1]; lg.z = lv[2]; lg.w = lv[3];
            gt.x = gv[0]; gt.y = gv[1]; gt.z = gv[2]; gt.w = gv[3];
            *(float4*)&lrow[j * 4] = lg;
            *(float4*)&orow[j * 4] = gt;
        }
    }
}

// ---------------------------------------------------------------------------
extern "C" void kernel_launch(void* const* d_in, const int* in_sizes, int n_in,
                              void* d_out, int out_size) {
    const float* x  = (const float*)d_in[0];
    const float* W1 = (const float*)d_in[1];
    const float* b1 = (const float*)d_in[2];
    const float* W2 = (const float*)d_in[3];
    const float* b2 = (const float*)d_in[4];
    float* out = (float*)d_out;

    static int init = 0;
    if (!init) {
        cudaFuncSetAttribute(fused_gate,
                             cudaFuncAttributeMaxDynamicSharedMemorySize,
                             SMEM_BYTES);
        init = 1;
    }

    prep_w<<<dim3(8, 32), 256>>>(W1);
    fused_gate<<<M_TOK / 128, 256, SMEM_BYTES>>>(x, b1, W2, b2, out);
}